// round 2
// baseline (speedup 1.0000x reference)
#include <cuda_runtime.h>
#include <math.h>
#include <stdint.h>

#define Bsz  128
#define Tlen 256
#define HID  512
#define GATE 1536
#define OUTN 64
#define MTOT (Bsz * Tlen)   // 32768

typedef unsigned long long ull;

// -------- static device scratch (no allocations allowed) --------
__device__ float    g_xg[(size_t)MTOT * GATE];    // 201 MB: gate preactivations (reused per layer)
__device__ float    g_hseq[(size_t)MTOT * HID];   // 67 MB: layer-0 outputs (input to layer-1 GEMM)
__device__ float    g_h[2][Bsz * HID];            // double-buffered hidden state
__device__ unsigned g_ctr[2];                     // grid barrier counters (one per layer)

// -------- packed fp32x2 helpers (Blackwell FFMA2) --------
__device__ __forceinline__ ull splat2(float a) {
    ull d; asm("mov.b64 %0, {%1, %1};" : "=l"(d) : "f"(a)); return d;
}
__device__ __forceinline__ ull pack2(float lo, float hi) {
    ull d; asm("mov.b64 %0, {%1, %2};" : "=l"(d) : "f"(lo), "f"(hi)); return d;
}
__device__ __forceinline__ ull fma2(ull a, ull b, ull c) {
    ull d; asm("fma.rn.f32x2 %0, %1, %2, %3;" : "=l"(d) : "l"(a), "l"(b), "l"(c)); return d;
}
__device__ __forceinline__ float2 unpack2(ull v) {
    float2 r; asm("mov.b64 {%0, %1}, %2;" : "=f"(r.x), "=f"(r.y) : "l"(v)); return r;
}

// ============================================================
// init: zero the grid-barrier counters (h zeroing happens inside recur)
// ============================================================
__global__ void init_k() {
    if (threadIdx.x < 2) g_ctr[threadIdx.x] = 0u;
}

// ============================================================
// xg GEMM: g_xg[m, g] = sum_k A[m,k] * W[g,k] + bias[g]
// A is [MTOT, K] row-major (x for layer 0, g_hseq for layer 1), W is [1536, K].
// 64x64 tile, Ktile=16, 256 threads, 4x4 per thread via FFMA2.
// ============================================================
__global__ __launch_bounds__(256) void gemm_xg_k(
    const float* __restrict__ Ain, const float* __restrict__ W,
    const float* __restrict__ bias, int K, int use_hseq)
{
    const float* __restrict__ A = use_hseq ? (const float*)g_hseq : Ain;
    __shared__ float As[16][68];
    __shared__ float Bs[16][68];

    int tid = threadIdx.x;
    int tx = tid & 15, ty = tid >> 4;
    int lr = tid >> 2, lc = tid & 3;
    int m0 = blockIdx.y << 6;
    int n0 = blockIdx.x << 6;

    const float4* Ap = (const float4*)(A + (size_t)(m0 + lr) * K) + lc;
    const float4* Bp = (const float4*)(W + (size_t)(n0 + lr) * K) + lc;

    ull acc[4][2];
#pragma unroll
    for (int i = 0; i < 4; i++) { acc[i][0] = 0ULL; acc[i][1] = 0ULL; }

    int nch = K >> 4;
    for (int c = 0; c < nch; c++) {
        float4 av = __ldg(Ap + c * 4);
        float4 bv = __ldg(Bp + c * 4);
        __syncthreads();
        int kb = lc << 2;
        As[kb + 0][lr] = av.x; As[kb + 1][lr] = av.y;
        As[kb + 2][lr] = av.z; As[kb + 3][lr] = av.w;
        Bs[kb + 0][lr] = bv.x; Bs[kb + 1][lr] = bv.y;
        Bs[kb + 2][lr] = bv.z; Bs[kb + 3][lr] = bv.w;
        __syncthreads();
#pragma unroll
        for (int kk = 0; kk < 16; kk++) {
            float4 a = *(const float4*)&As[kk][ty << 2];
            const ull* bp = (const ull*)&Bs[kk][tx << 2];
            ull b01 = bp[0], b23 = bp[1];
            ull a0 = splat2(a.x), a1 = splat2(a.y), a2 = splat2(a.z), a3 = splat2(a.w);
            acc[0][0] = fma2(a0, b01, acc[0][0]); acc[0][1] = fma2(a0, b23, acc[0][1]);
            acc[1][0] = fma2(a1, b01, acc[1][0]); acc[1][1] = fma2(a1, b23, acc[1][1]);
            acc[2][0] = fma2(a2, b01, acc[2][0]); acc[2][1] = fma2(a2, b23, acc[2][1]);
            acc[3][0] = fma2(a3, b01, acc[3][0]); acc[3][1] = fma2(a3, b23, acc[3][1]);
        }
    }

    float4 bb = __ldg((const float4*)(bias + n0) + tx);
#pragma unroll
    for (int i = 0; i < 4; i++) {
        float2 c01 = unpack2(acc[i][0]);
        float2 c23 = unpack2(acc[i][1]);
        float4 o;
        o.x = c01.x + bb.x; o.y = c01.y + bb.y;
        o.z = c23.x + bb.z; o.w = c23.y + bb.w;
        *((float4*)(g_xg + (size_t)(m0 + (ty << 2) + i) * GATE + n0) + tx) = o;
    }
}

// ============================================================
// Persistent recurrent kernel: one launch runs all 256 steps of one layer.
// Grid: 128 blocks = 4 batch-tiles(32) x 32 j-tiles(16 j each -> 48 gate rows).
// W_hh slice (48 rows x 512, j-pair packed for FFMA2) lives in SMEM for all steps.
// One atomic grid barrier per step; h double-buffered in global (L2-resident).
// ============================================================
#define WS_BYTES  (3 * 8 * 256 * 16)            // 96 KB packed weights
#define HS_FLOATS (512 * 33)                    // padded transposed h tile
#define RECUR_SMEM (WS_BYTES + HS_FLOATS * 4)   // 98304 + 67584 = 165888 B

__global__ __launch_bounds__(256, 1) void recur_k(
    const float* __restrict__ Whh, const float* __restrict__ bhh, int layer)
{
    extern __shared__ char smraw[];
    ulonglong2* ws2 = (ulonglong2*)smraw;                 // [3][8][256] j-pair packed
    float* hs = (float*)(smraw + WS_BYTES);               // hs[k][b], stride 33

    int tid = threadIdx.x;
    int bt = blockIdx.x >> 5;   // batch tile 0..3
    int jt = blockIdx.x & 31;   // j tile 0..31
    int bg0 = bt << 5;

    // ---- one-time: pack W_hh rows {jt*16+jj, +8} for gates r,z,n into SMEM ----
    for (int i = tid; i < 3 * 8 * 256; i += 256) {
        int k2 = i & 255;
        int jj2 = (i >> 8) & 7;
        int g = i >> 11;
        int r0 = g * HID + (jt << 4) + jj2;
        const float2* p0 = (const float2*)(Whh + (size_t)r0 * HID);
        const float2* p1 = (const float2*)(Whh + (size_t)(r0 + 8) * HID);
        float2 a = __ldg(p0 + k2);
        float2 bq = __ldg(p1 + k2);
        ulonglong2 w;
        w.x = pack2(a.x, bq.x);   // (w_j0[2k], w_j1[2k])
        w.y = pack2(a.y, bq.y);   // (w_j0[2k+1], w_j1[2k+1])
        ws2[i] = w;
    }

    int b  = tid & 31;
    int jj = tid >> 5;
    int jg0 = (jt << 4) + jj;
    int jg1 = jg0 + 8;
    int bg = bg0 + b;

    ull bias_r = pack2(__ldg(bhh + jg0),            __ldg(bhh + jg1));
    ull bias_z = pack2(__ldg(bhh + HID + jg0),      __ldg(bhh + HID + jg1));
    ull bias_n = pack2(__ldg(bhh + 2 * HID + jg0),  __ldg(bhh + 2 * HID + jg1));

    unsigned* ctr = &g_ctr[layer];

    // ---- phase 0: zero this block's slice of h buffer 0 ----
    for (int i = tid; i < 512; i += 256) {
        int bb2 = i & 31, jl = i >> 5;
        g_h[0][(bg0 + bb2) * HID + (jt << 4) + jl] = 0.0f;
    }
    __threadfence();
    __syncthreads();
    if (tid == 0) {
        atomicAdd(ctr, 1u);
        while (*((volatile unsigned*)ctr) < 128u) {}
    }
    __syncthreads();

    const ulonglong2* wr = ws2 + ((0 * 8 + jj) << 8);
    const ulonglong2* wz = ws2 + ((1 * 8 + jj) << 8);
    const ulonglong2* wn = ws2 + ((2 * 8 + jj) << 8);

    for (int t = 0; t < Tlen; t++) {
        int rb = t & 1, wb = rb ^ 1;

        // ---- load h tile [32 x 512] -> transposed hs[k][b] (coalesced + 33-pad) ----
        const float4* hsrc = (const float4*)(g_h[rb] + (size_t)bg0 * HID);
        for (int i = tid; i < 32 * 128; i += 256) {
            int row = i >> 7, kq = i & 127;
            float4 v = __ldcg(hsrc + row * 128 + kq);
            int kb = kq << 2;
            hs[(kb + 0) * 33 + row] = v.x;
            hs[(kb + 1) * 33 + row] = v.y;
            hs[(kb + 2) * 33 + row] = v.z;
            hs[(kb + 3) * 33 + row] = v.w;
        }
        __syncthreads();

        // ---- hg = h @ Whh^T for gate rows (r,z,n) x (jg0,jg1), FFMA2 packed ----
        ull accr = bias_r, accz = bias_z, accn = bias_n;
        const float* hp = hs + b;
#pragma unroll 8
        for (int k2 = 0; k2 < 256; k2++) {
            ull h0 = splat2(hp[0]);
            ull h1 = splat2(hp[33]);
            hp += 66;
            ulonglong2 w = wr[k2];
            accr = fma2(w.x, h0, accr); accr = fma2(w.y, h1, accr);
            w = wz[k2];
            accz = fma2(w.x, h0, accz); accz = fma2(w.y, h1, accz);
            w = wn[k2];
            accn = fma2(w.x, h0, accn); accn = fma2(w.y, h1, accn);
        }
        float2 hr = unpack2(accr), hz = unpack2(accz), hn = unpack2(accn);

        // ---- gates + state update ----
        size_t row = ((size_t)bg * Tlen + t) * GATE;
        float xr0 = __ldg(g_xg + row + jg0);
        float xz0 = __ldg(g_xg + row + HID + jg0);
        float xn0 = __ldg(g_xg + row + 2 * HID + jg0);
        float xr1 = __ldg(g_xg + row + jg1);
        float xz1 = __ldg(g_xg + row + HID + jg1);
        float xn1 = __ldg(g_xg + row + 2 * HID + jg1);

        float r0v = 1.0f / (1.0f + __expf(-(xr0 + hr.x)));
        float z0v = 1.0f / (1.0f + __expf(-(xz0 + hz.x)));
        float n0v = tanhf(xn0 + r0v * hn.x);
        float ho0 = hs[jg0 * 33 + b];
        float hnew0 = (1.0f - z0v) * n0v + z0v * ho0;

        float r1v = 1.0f / (1.0f + __expf(-(xr1 + hr.y)));
        float z1v = 1.0f / (1.0f + __expf(-(xz1 + hz.y)));
        float n1v = tanhf(xn1 + r1v * hn.y);
        float ho1 = hs[jg1 * 33 + b];
        float hnew1 = (1.0f - z1v) * n1v + z1v * ho1;

        g_h[wb][bg * HID + jg0] = hnew0;
        g_h[wb][bg * HID + jg1] = hnew1;
        if (layer == 0) {
            size_t srow = ((size_t)bg * Tlen + t) * HID;
            g_hseq[srow + jg0] = hnew0;
            g_hseq[srow + jg1] = hnew1;
        }

        // ---- grid barrier (release: fence + atomic arrive; acquire: spin) ----
        __threadfence();
        __syncthreads();
        if (tid == 0) {
            atomicAdd(ctr, 1u);
            unsigned target = 128u * (unsigned)(t + 2);
            while (*((volatile unsigned*)ctr) < target) {}
        }
        __syncthreads();
    }
}

// ============================================================
// output: yhat[b,o] = h_final[b,:] . W_out[o,:] + b_out[o]
// Final h of layer 1 recurrence lives in g_h[0] (Tlen even).
// ============================================================
__global__ __launch_bounds__(64) void out_k(
    const float* __restrict__ Wout, const float* __restrict__ bout,
    float* __restrict__ out)
{
    __shared__ float hrow[HID];
    int bg = blockIdx.x, tid = threadIdx.x;
    for (int i = tid; i < HID; i += 64) hrow[i] = g_h[0][bg * HID + i];
    __syncthreads();
    float acc = __ldg(bout + tid);
    const float* w = Wout + (size_t)tid * HID;
#pragma unroll 8
    for (int j = 0; j < HID; j++) acc += hrow[j] * __ldg(w + j);
    out[bg * OUTN + tid] = acc;
}

// ============================================================
extern "C" void kernel_launch(void* const* d_in, const int* in_sizes, int n_in,
                              void* d_out, int out_size)
{
    const float* x     = (const float*)d_in[0];
    const float* W_ih0 = (const float*)d_in[1];
    const float* W_hh0 = (const float*)d_in[2];
    const float* b_ih0 = (const float*)d_in[3];
    const float* b_hh0 = (const float*)d_in[4];
    const float* W_ih1 = (const float*)d_in[5];
    const float* W_hh1 = (const float*)d_in[6];
    const float* b_ih1 = (const float*)d_in[7];
    const float* b_hh1 = (const float*)d_in[8];
    const float* W_out = (const float*)d_in[9];
    const float* b_out = (const float*)d_in[10];
    float* out = (float*)d_out;

    cudaFuncSetAttribute(recur_k, cudaFuncAttributeMaxDynamicSharedMemorySize,
                         RECUR_SMEM);

    init_k<<<1, 32>>>();

    // layer 0
    gemm_xg_k<<<dim3(GATE / 64, MTOT / 64), 256>>>(x, W_ih0, b_ih0, 256, 0);
    recur_k<<<128, 256, RECUR_SMEM>>>(W_hh0, b_hh0, 0);

    // layer 1
    gemm_xg_k<<<dim3(GATE / 64, MTOT / 64), 256>>>(nullptr, W_ih1, b_ih1, 512, 1);
    recur_k<<<128, 256, RECUR_SMEM>>>(W_hh1, b_hh1, 1);

    // output projection
    out_k<<<Bsz, OUTN>>>(W_out, b_out, out);
}

// round 4
// speedup vs baseline: 1.1485x; 1.1485x over previous
#include <cuda_runtime.h>
#include <math.h>
#include <stdint.h>

#define Bsz  128
#define Tlen 256
#define HID  512
#define GATE 1536
#define OUTN 64
#define MTOT (Bsz * Tlen)   // 32768

typedef unsigned long long ull;

// -------- static device scratch (no allocations allowed) --------
// g_xg  : [t][gate][b]  (batch innermost, coalesced for recurrence)
__device__ float    g_xg[(size_t)Tlen * GATE * Bsz];    // 201 MB
// g_hseq: [t][j][b]     layer-0 outputs, read by layer-1 gemm
__device__ float    g_hseq[(size_t)Tlen * HID * Bsz];   // 67 MB
// g_h   : [buf][j][b]   double-buffered hidden state, batch innermost
__device__ float    g_h[2][HID * Bsz];
__device__ unsigned g_ctr[2];                           // grid barrier counters

// -------- packed fp32x2 helpers (Blackwell FFMA2) --------
__device__ __forceinline__ ull splat2(float a) {
    ull d; asm("mov.b64 %0, {%1, %1};" : "=l"(d) : "f"(a)); return d;
}
__device__ __forceinline__ ull pack2(float lo, float hi) {
    ull d; asm("mov.b64 %0, {%1, %2};" : "=l"(d) : "f"(lo), "f"(hi)); return d;
}
__device__ __forceinline__ ull fma2(ull a, ull b, ull c) {
    ull d; asm("fma.rn.f32x2 %0, %1, %2, %3;" : "=l"(d) : "l"(a), "l"(b), "l"(c)); return d;
}
__device__ __forceinline__ float2 unpack2(ull v) {
    float2 r; asm("mov.b64 {%0, %1}, %2;" : "=f"(r.x), "=f"(r.y) : "l"(v)); return r;
}

// -------- release/acquire grid-barrier primitives (no L1 flush) --------
__device__ __forceinline__ void bar_arrive(unsigned* ctr) {
    asm volatile("red.release.gpu.global.add.u32 [%0], %1;"
                 :: "l"(ctr), "r"(1u) : "memory");
}
__device__ __forceinline__ unsigned bar_poll(unsigned* ctr) {
    unsigned v;
    asm volatile("ld.acquire.gpu.global.u32 %0, [%1];"
                 : "=r"(v) : "l"(ctr) : "memory");
    return v;
}

// ============================================================
__global__ void init_k() {
    if (threadIdx.x < 2) g_ctr[threadIdx.x] = 0u;
}

// ============================================================
// xg GEMM, transposed output: g_xg[t][g][b] = sum_k src[b,t,k] * W[g,k] + bias[g]
// Tile: 64 g x 64 b, fixed t.  layer1=0: src = x rows (b*T+t).  layer1=1: src = g_hseq[t][k][b].
// 256 threads, 4x4 per thread via FFMA2.
// ============================================================
__global__ __launch_bounds__(256) void gemm_xgT_k(
    const float* __restrict__ Ain, const float* __restrict__ W,
    const float* __restrict__ bias, int K, int layer1)
{
    __shared__ float Ws[16][68];   // [k][g]
    __shared__ float Hs[16][68];   // [k][b]

    int tid = threadIdx.x;
    int g0 = blockIdx.x << 6;
    int t  = blockIdx.y >> 1;
    int b0 = (blockIdx.y & 1) << 6;

    int lr = tid >> 2, lc = tid & 3;           // weight / layer0 loaders
    int kk = tid >> 4, bq = tid & 15;          // layer1 loader + compute map
    int gq = tid >> 4;                         // compute: g-quad
    // bq doubles as compute b-quad

    const float4* Wp = (const float4*)(W + (size_t)(g0 + lr) * K) + lc;
    const float4* Xp = (const float4*)(Ain + ((size_t)(b0 + lr) * Tlen + t) * K) + lc;
    const float4* Hq = (const float4*)g_hseq + (size_t)t * HID * (Bsz / 4)
                       + (size_t)kk * (Bsz / 4) + (b0 >> 2) + bq;

    ull acc[4][2];
#pragma unroll
    for (int i = 0; i < 4; i++) { acc[i][0] = 0ULL; acc[i][1] = 0ULL; }

    int nch = K >> 4;
    for (int c = 0; c < nch; c++) {
        float4 wv = __ldg(Wp + c * 4);
        float4 hv;
        if (!layer1) hv = __ldg(Xp + c * 4);
        else         hv = __ldg(Hq + (size_t)c * 16 * (Bsz / 4));
        __syncthreads();
        int kb = lc << 2;
        Ws[kb + 0][lr] = wv.x; Ws[kb + 1][lr] = wv.y;
        Ws[kb + 2][lr] = wv.z; Ws[kb + 3][lr] = wv.w;
        if (!layer1) {
            Hs[kb + 0][lr] = hv.x; Hs[kb + 1][lr] = hv.y;
            Hs[kb + 2][lr] = hv.z; Hs[kb + 3][lr] = hv.w;
        } else {
            *(float4*)&Hs[kk][bq << 2] = hv;
        }
        __syncthreads();
#pragma unroll
        for (int k2 = 0; k2 < 16; k2++) {
            float4 a = *(const float4*)&Ws[k2][gq << 2];
            const ull* hp2 = (const ull*)&Hs[k2][bq << 2];
            ull b01 = hp2[0], b23 = hp2[1];
            ull a0 = splat2(a.x), a1 = splat2(a.y), a2 = splat2(a.z), a3 = splat2(a.w);
            acc[0][0] = fma2(a0, b01, acc[0][0]); acc[0][1] = fma2(a0, b23, acc[0][1]);
            acc[1][0] = fma2(a1, b01, acc[1][0]); acc[1][1] = fma2(a1, b23, acc[1][1]);
            acc[2][0] = fma2(a2, b01, acc[2][0]); acc[2][1] = fma2(a2, b23, acc[2][1]);
            acc[3][0] = fma2(a3, b01, acc[3][0]); acc[3][1] = fma2(a3, b23, acc[3][1]);
        }
    }

#pragma unroll
    for (int i = 0; i < 4; i++) {
        int g = g0 + (gq << 2) + i;
        float bg_ = __ldg(bias + g);
        float2 c01 = unpack2(acc[i][0]);
        float2 c23 = unpack2(acc[i][1]);
        float4 o;
        o.x = c01.x + bg_; o.y = c01.y + bg_;
        o.z = c23.x + bg_; o.w = c23.y + bg_;
        *(float4*)(g_xg + ((size_t)t * GATE + g) * Bsz + b0 + (bq << 2)) = o;
    }
}

// ============================================================
// Persistent recurrent kernel: one launch runs all 256 steps of one layer.
// Grid: 128 blocks = 4 batch-tiles(32b) x 32 j-tiles(16 j -> 48 gate rows).
// W_hh slice (j-pair packed, FFMA2) resident in SMEM.
// One release/acquire grid barrier per step; h double-buffered [j][b] in global.
// ============================================================
#define WS_BYTES  (3 * 8 * 256 * 16)            // 96 KB packed weights
#define HSTRIDE   36
#define HS_FLOATS (512 * HSTRIDE)               // 18432 floats
#define RECUR_SMEM (WS_BYTES + HS_FLOATS * 4)   // 98304 + 73728 = 172032 B

__global__ __launch_bounds__(256, 1) void recur_k(
    const float* __restrict__ Whh, const float* __restrict__ bhh, int layer)
{
    extern __shared__ char smraw[];
    ulonglong2* ws2 = (ulonglong2*)smraw;                 // [3][8][256] j-pair packed
    float* hs = (float*)(smraw + WS_BYTES);               // hs[k][b], stride HSTRIDE

    int tid = threadIdx.x;
    int bt = blockIdx.x >> 5;   // batch tile 0..3
    int jt = blockIdx.x & 31;   // j tile 0..31
    int bg0 = bt << 5;

    // ---- one-time: pack W_hh rows {jt*16+jj, +8} for gates r,z,n into SMEM ----
    for (int i = tid; i < 3 * 8 * 256; i += 256) {
        int k2 = i & 255;
        int jj2 = (i >> 8) & 7;
        int g = i >> 11;
        int r0 = g * HID + (jt << 4) + jj2;
        const float2* p0 = (const float2*)(Whh + (size_t)r0 * HID);
        const float2* p1 = (const float2*)(Whh + (size_t)(r0 + 8) * HID);
        float2 a = __ldg(p0 + k2);
        float2 bq = __ldg(p1 + k2);
        ulonglong2 w;
        w.x = pack2(a.x, bq.x);
        w.y = pack2(a.y, bq.y);
        ws2[i] = w;
    }

    int b  = tid & 31;
    int jj = tid >> 5;
    int jg0 = (jt << 4) + jj;
    int jg1 = jg0 + 8;
    int bg = bg0 + b;

    ull bias_r = pack2(__ldg(bhh + jg0),            __ldg(bhh + jg1));
    ull bias_z = pack2(__ldg(bhh + HID + jg0),      __ldg(bhh + HID + jg1));
    ull bias_n = pack2(__ldg(bhh + 2 * HID + jg0),  __ldg(bhh + 2 * HID + jg1));

    unsigned* ctr = &g_ctr[layer];

    // ---- phase 0: zero this block's slice of h buffer 0 ([j][b] layout) ----
    for (int i = tid; i < 512; i += 256) {
        int jl = i >> 5, bb2 = i & 31;
        g_h[0][((jt << 4) + jl) * Bsz + bg0 + bb2] = 0.0f;
    }
    __syncthreads();
    if (tid == 0) {
        bar_arrive(ctr);
        while (bar_poll(ctr) < 128u) {}
    }
    __syncthreads();

    const ulonglong2* wr = ws2 + ((0 * 8 + jj) << 8);
    const ulonglong2* wz = ws2 + ((1 * 8 + jj) << 8);
    const ulonglong2* wn = ws2 + ((2 * 8 + jj) << 8);

    for (int t = 0; t < Tlen; t++) {
        int rb = t & 1, wb = rb ^ 1;

        // ---- xg loads first (coalesced, independent of h — overlap with h reload) ----
        size_t xrow = (size_t)t * GATE * Bsz;
        float xr0 = __ldg(g_xg + xrow + (size_t)jg0 * Bsz + bg);
        float xz0 = __ldg(g_xg + xrow + (size_t)(HID + jg0) * Bsz + bg);
        float xn0 = __ldg(g_xg + xrow + (size_t)(2 * HID + jg0) * Bsz + bg);
        float xr1 = __ldg(g_xg + xrow + (size_t)jg1 * Bsz + bg);
        float xz1 = __ldg(g_xg + xrow + (size_t)(HID + jg1) * Bsz + bg);
        float xn1 = __ldg(g_xg + xrow + (size_t)(2 * HID + jg1) * Bsz + bg);

        // ---- load h tile: all 512 j x this block's 32 b -> hs[k][b] (coalesced) ----
        const float4* hsrc = (const float4*)(g_h[rb]);
        for (int i = tid; i < 512 * 8; i += 256) {
            int k = i >> 3, q = i & 7;
            float4 v = __ldcg(hsrc + k * (Bsz / 4) + (bg0 >> 2) + q);
            *(float4*)&hs[k * HSTRIDE + (q << 2)] = v;
        }
        __syncthreads();

        // ---- hg = h @ Whh^T for gate rows (r,z,n) x (jg0,jg1), FFMA2 packed ----
        ull accr = bias_r, accz = bias_z, accn = bias_n;
        const float* hp = hs + b;
#pragma unroll 8
        for (int k2 = 0; k2 < 256; k2++) {
            ull h0 = splat2(hp[0]);
            ull h1 = splat2(hp[HSTRIDE]);
            hp += 2 * HSTRIDE;
            ulonglong2 w = wr[k2];
            accr = fma2(w.x, h0, accr); accr = fma2(w.y, h1, accr);
            w = wz[k2];
            accz = fma2(w.x, h0, accz); accz = fma2(w.y, h1, accz);
            w = wn[k2];
            accn = fma2(w.x, h0, accn); accn = fma2(w.y, h1, accn);
        }
        float2 hr = unpack2(accr), hz = unpack2(accz), hn = unpack2(accn);

        // ---- gates + state update ----
        float r0v = 1.0f / (1.0f + __expf(-(xr0 + hr.x)));
        float z0v = 1.0f / (1.0f + __expf(-(xz0 + hz.x)));
        float n0v = tanhf(xn0 + r0v * hn.x);
        float ho0 = hs[jg0 * HSTRIDE + b];
        float hnew0 = (1.0f - z0v) * n0v + z0v * ho0;

        float r1v = 1.0f / (1.0f + __expf(-(xr1 + hr.y)));
        float z1v = 1.0f / (1.0f + __expf(-(xz1 + hz.y)));
        float n1v = tanhf(xn1 + r1v * hn.y);
        float ho1 = hs[jg1 * HSTRIDE + b];
        float hnew1 = (1.0f - z1v) * n1v + z1v * ho1;

        // ---- coalesced stores ([j][b] layouts) ----
        g_h[wb][jg0 * Bsz + bg] = hnew0;
        g_h[wb][jg1 * Bsz + bg] = hnew1;
        if (layer == 0) {
            size_t srow = (size_t)t * HID * Bsz;
            g_hseq[srow + (size_t)jg0 * Bsz + bg] = hnew0;
            g_hseq[srow + (size_t)jg1 * Bsz + bg] = hnew1;
        }

        // ---- grid barrier: release-arrive + acquire-spin (no L1 flush) ----
        __syncthreads();
        if (tid == 0) {
            bar_arrive(ctr);
            unsigned target = 128u * (unsigned)(t + 2);
            while (bar_poll(ctr) < target) {}
        }
        __syncthreads();
    }
}

// ============================================================
// output: yhat[b,o] = h_final[b,:] . W_out[o,:] + b_out[o]
// Final h of layer 1 lives in g_h[0] (Tlen even), layout [j][b].
// ============================================================
__global__ __launch_bounds__(64) void out_k(
    const float* __restrict__ Wout, const float* __restrict__ bout,
    float* __restrict__ out)
{
    __shared__ float hrow[HID];
    int bg = blockIdx.x, tid = threadIdx.x;
    for (int i = tid; i < HID; i += 64) hrow[i] = g_h[0][i * Bsz + bg];
    __syncthreads();
    float acc = __ldg(bout + tid);
    const float* w = Wout + (size_t)tid * HID;
#pragma unroll 8
    for (int j = 0; j < HID; j++) acc += hrow[j] * __ldg(w + j);
    out[bg * OUTN + tid] = acc;
}

// ============================================================
extern "C" void kernel_launch(void* const* d_in, const int* in_sizes, int n_in,
                              void* d_out, int out_size)
{
    const float* x     = (const float*)d_in[0];
    const float* W_ih0 = (const float*)d_in[1];
    const float* W_hh0 = (const float*)d_in[2];
    const float* b_ih0 = (const float*)d_in[3];
    const float* b_hh0 = (const float*)d_in[4];
    const float* W_ih1 = (const float*)d_in[5];
    const float* W_hh1 = (const float*)d_in[6];
    const float* b_ih1 = (const float*)d_in[7];
    const float* b_hh1 = (const float*)d_in[8];
    const float* W_out = (const float*)d_in[9];
    const float* b_out = (const float*)d_in[10];
    float* out = (float*)d_out;

    cudaFuncSetAttribute(recur_k, cudaFuncAttributeMaxDynamicSharedMemorySize,
                         RECUR_SMEM);

    init_k<<<1, 32>>>();

    // layer 0
    gemm_xgT_k<<<dim3(GATE / 64, Tlen * 2), 256>>>(x, W_ih0, b_ih0, 256, 0);
    recur_k<<<128, 256, RECUR_SMEM>>>(W_hh0, b_hh0, 0);

    // layer 1
    gemm_xgT_k<<<dim3(GATE / 64, Tlen * 2), 256>>>(nullptr, W_ih1, b_ih1, 512, 1);
    recur_k<<<128, 256, RECUR_SMEM>>>(W_hh1, b_hh1, 1);

    // output projection
    out_k<<<Bsz, OUTN>>>(W_out, b_out, out);
}

// round 6
// speedup vs baseline: 1.3143x; 1.1443x over previous
#include <cuda_runtime.h>
#include <cuda_bf16.h>
#include <math.h>
#include <stdint.h>

#define Bsz  128
#define Tlen 256
#define HID  512
#define GATE 1536
#define OUTN 64
#define INPUTK 256

typedef unsigned long long ull;

// -------- static device scratch --------
__device__ float g_xg[(size_t)Tlen * GATE * Bsz];     // [t][g][b]
__device__ float g_hseq[(size_t)Tlen * HID * Bsz];    // [t][k][b]
__device__ ull   g_h2[2][256 * 128];                  // [buf][k2][b] packed (h[2k2],h[2k2+1])
__device__ unsigned g_ctr[2];

// -------- fp32x2 helpers --------
__device__ __forceinline__ ull pack2(float lo, float hi) {
    ull d; asm("mov.b64 %0, {%1, %2};" : "=l"(d) : "f"(lo), "f"(hi)); return d;
}
__device__ __forceinline__ ull fma2(ull a, ull b, ull c) {
    ull d; asm("fma.rn.f32x2 %0, %1, %2, %3;" : "=l"(d) : "l"(a), "l"(b), "l"(c)); return d;
}
__device__ __forceinline__ float2 unpack2(ull v) {
    float2 r; asm("mov.b64 {%0, %1}, %2;" : "=f"(r.x), "=f"(r.y) : "l"(v)); return r;
}

// -------- grid barrier --------
__device__ __forceinline__ void bar_arrive(unsigned* ctr) {
    asm volatile("red.release.gpu.global.add.u32 [%0], %1;" :: "l"(ctr), "r"(1u) : "memory");
}
__device__ __forceinline__ unsigned bar_poll(unsigned* ctr) {
    unsigned v;
    asm volatile("ld.acquire.gpu.global.u32 %0, [%1];" : "=r"(v) : "l"(ctr) : "memory");
    return v;
}

// -------- smem / mma helpers (generic sm_103-safe: ldmatrix + mma.sync) --------
__device__ __forceinline__ uint32_t smem_u32(const void* p) {
    uint32_t a;
    asm("{ .reg .u64 t; cvta.to.shared.u64 t, %1; cvt.u32.u64 %0, t; }" : "=r"(a) : "l"(p));
    return a;
}
__device__ __forceinline__ void ldsm4(unsigned* r, uint32_t addr) {
    asm volatile("ldmatrix.sync.aligned.m8n8.x4.shared.b16 {%0,%1,%2,%3}, [%4];"
                 : "=r"(r[0]), "=r"(r[1]), "=r"(r[2]), "=r"(r[3]) : "r"(addr));
}
__device__ __forceinline__ void mma_bf16(float* d, const unsigned* a,
                                         unsigned b0, unsigned b1) {
    asm volatile(
        "mma.sync.aligned.m16n8k16.row.col.f32.bf16.bf16.f32 "
        "{%0,%1,%2,%3}, {%4,%5,%6,%7}, {%8,%9}, {%0,%1,%2,%3};"
        : "+f"(d[0]), "+f"(d[1]), "+f"(d[2]), "+f"(d[3])
        : "r"(a[0]), "r"(a[1]), "r"(a[2]), "r"(a[3]), "r"(b0), "r"(b1));
}

// bf16 hi/lo split of two floats -> two packed bf16x2 words (a low half, b high half)
__device__ __forceinline__ void cvt2(float a, float b, unsigned& hi, unsigned& lo) {
    __nv_bfloat16 ah = __float2bfloat16(a);
    __nv_bfloat16 bh = __float2bfloat16(b);
    __nv_bfloat16 al = __float2bfloat16(a - __bfloat162float(ah));
    __nv_bfloat16 bl = __float2bfloat16(b - __bfloat162float(bh));
    hi = ((unsigned)__bfloat16_as_ushort(bh) << 16) | __bfloat16_as_ushort(ah);
    lo = ((unsigned)__bfloat16_as_ushort(bl) << 16) | __bfloat16_as_ushort(al);
}

__global__ void init_k() { if (threadIdx.x < 2) g_ctr[threadIdx.x] = 0u; }

// ============================================================
// Tensor-core xg GEMM via mma.sync bf16 hi/lo split (3 products).
// C[g][b] (128x128 per block, fixed t) = W[g,:] . src[b,t,:] ; +bias in epilogue.
// 8 warps: warp (wm=wid&3, wn=wid>>2) owns 32g x 64b.
// SMEM tiles: 128 rows x 32 k bf16, row stride 40 elems (80 B, ldmatrix conflict-free).
// ============================================================
#define RS 40                     // smem row stride in bf16 elems (80 B)
#define SM_AHI 0
#define SM_ALO 10240
#define SM_BHI 20480
#define SM_BLO 30720
#define SM_GEMM_TOTAL 40960       // also reused as 128x68 f32 stage (34816 B)

__global__ __launch_bounds__(256) void gemm_tc_k(
    const float* __restrict__ src, const float* __restrict__ W,
    const float* __restrict__ bias, int K, int transB)
{
    extern __shared__ char sm[];
    uint32_t smb = smem_u32(sm);
    int tid = threadIdx.x;
    int lane = tid & 31, wid = tid >> 5;
    int wm = wid & 3, wn = wid >> 2;
    int g0 = blockIdx.x << 7;
    int t  = blockIdx.y;

    float acc[2][8][4];
#pragma unroll
    for (int a = 0; a < 2; a++)
#pragma unroll
        for (int b = 0; b < 8; b++)
#pragma unroll
            for (int c = 0; c < 4; c++) acc[a][b][c] = 0.0f;

    // ldmatrix lane addressing: row = lane&15, col byte = (lane>>4)*16
    uint32_t lrow = lane & 15;
    uint32_t lcolb = (lane >> 4) * 16;

    int nch = K >> 5;
    for (int kc = 0; kc < nch; kc++) {
        int k0 = kc << 5;

        // ---- A tile: W rows g0..g0+127, cols k0..k0+31 ----
        {
            const float* abase = W + (size_t)g0 * K + k0;
            for (int i = tid; i < 1024; i += 256) {
                int r = i >> 3, q = i & 7;
                float4 v = __ldg((const float4*)(abase + (size_t)r * K) + q);
                unsigned h0, l0, h1, l1;
                cvt2(v.x, v.y, h0, l0);
                cvt2(v.z, v.w, h1, l1);
                *(uint2*)(sm + SM_AHI + r * 80 + q * 8) = make_uint2(h0, h1);
                *(uint2*)(sm + SM_ALO + r * 80 + q * 8) = make_uint2(l0, l1);
            }
        }
        // ---- B tile: 128 b rows, cols k0..k0+31 ----
        if (!transB) {
            const float* bbase = src + (size_t)t * INPUTK + k0;
            for (int i = tid; i < 1024; i += 256) {
                int r = i >> 3, q = i & 7;
                float4 v = __ldg((const float4*)(bbase + (size_t)r * (Tlen * INPUTK)) + q);
                unsigned h0, l0, h1, l1;
                cvt2(v.x, v.y, h0, l0);
                cvt2(v.z, v.w, h1, l1);
                *(uint2*)(sm + SM_BHI + r * 80 + q * 8) = make_uint2(h0, h1);
                *(uint2*)(sm + SM_BLO + r * 80 + q * 8) = make_uint2(l0, l1);
            }
        } else {
            // g_hseq [t][k][b]: coalesced along b
            int b = tid & 127, kh = tid >> 7;
            const float* hp = g_hseq + ((size_t)t * HID + k0 + kh * 16) * Bsz + b;
#pragma unroll
            for (int q = 0; q < 8; q++) {
                float f0 = __ldg(hp + (2 * q + 0) * Bsz);
                float f1 = __ldg(hp + (2 * q + 1) * Bsz);
                unsigned hh, ll;
                cvt2(f0, f1, hh, ll);
                int colb = (kh * 16 + 2 * q) * 2;
                *(unsigned*)(sm + SM_BHI + b * 80 + colb) = hh;
                *(unsigned*)(sm + SM_BLO + b * 80 + colb) = ll;
            }
        }
        __syncthreads();

#pragma unroll
        for (int ks = 0; ks < 2; ks++) {
            uint32_t kb = ks * 32 + lcolb;
            unsigned ahi[2][4], alo[2][4];
#pragma unroll
            for (int mt = 0; mt < 2; mt++) {
                uint32_t rowoff = (wm * 32 + mt * 16 + lrow) * 80 + kb;
                ldsm4(ahi[mt], smb + SM_AHI + rowoff);
                ldsm4(alo[mt], smb + SM_ALO + rowoff);
            }
#pragma unroll
            for (int nt = 0; nt < 4; nt++) {
                uint32_t rowoff = (wn * 64 + nt * 16 + lrow) * 80 + kb;
                unsigned bhi[4], blo[4];
                ldsm4(bhi, smb + SM_BHI + rowoff);
                ldsm4(blo, smb + SM_BLO + rowoff);
#pragma unroll
                for (int mt = 0; mt < 2; mt++) {
                    float* a0 = acc[mt][nt * 2 + 0];
                    float* a1 = acc[mt][nt * 2 + 1];
                    mma_bf16(a0, ahi[mt], bhi[0], bhi[2]);
                    mma_bf16(a0, ahi[mt], blo[0], blo[2]);
                    mma_bf16(a0, alo[mt], bhi[0], bhi[2]);
                    mma_bf16(a1, ahi[mt], bhi[1], bhi[3]);
                    mma_bf16(a1, ahi[mt], blo[1], blo[3]);
                    mma_bf16(a1, alo[mt], bhi[1], bhi[3]);
                }
            }
        }
        __syncthreads();
    }

    // ---- epilogue: stage each b-half through SMEM, fuse bias, coalesced STG ----
    float* stage = (float*)sm;
#pragma unroll
    for (int p = 0; p < 2; p++) {
        if (wn == p) {
#pragma unroll
            for (int mt = 0; mt < 2; mt++)
#pragma unroll
                for (int nn = 0; nn < 8; nn++) {
                    int gl = wm * 32 + mt * 16 + (lane >> 2);
                    int bl = nn * 8 + 2 * (lane & 3);
                    float* s0 = &stage[gl * 68 + bl];
                    s0[0] = acc[mt][nn][0];
                    s0[1] = acc[mt][nn][1];
                    s0[68 * 8 + 0] = acc[mt][nn][2];
                    s0[68 * 8 + 1] = acc[mt][nn][3];
                }
        }
        __syncthreads();
        for (int i = tid; i < 2048; i += 256) {
            int r = i >> 4, c4 = i & 15;
            float4 v = *(const float4*)&stage[r * 68 + c4 * 4];
            float bv = __ldg(bias + g0 + r);
            v.x += bv; v.y += bv; v.z += bv; v.w += bv;
            *(float4*)(g_xg + ((size_t)t * GATE + g0 + r) * Bsz + p * 64 + c4 * 4) = v;
        }
        __syncthreads();
    }
}

// ============================================================
// Persistent recurrence, k-pair packed.
// 128 blocks = 4 bt(32 b) x 32 jt(16 j). Thread: b=tid&31, jj=tid>>5,
// handles j pair (jt*16+2jj, +1) x 3 gates. Accs hold even/odd-k partials.
// ============================================================
#define WS_BYTES  (3 * 8 * 256 * 16)
#define HS_ULLS   (256 * 34)
#define RECUR_SMEM (WS_BYTES + HS_ULLS * 8)   // 98304 + 69632 = 167936

__global__ __launch_bounds__(256, 1) void recur_k(
    const float* __restrict__ Whh, const float* __restrict__ bhh, int layer)
{
    extern __shared__ char smraw[];
    ulonglong2* ws2 = (ulonglong2*)smraw;         // [3][8][256]: (rowA k-pair, rowB k-pair)
    ull* hsu = (ull*)(smraw + WS_BYTES);          // [k2][b] stride 34

    int tid = threadIdx.x;
    int bt = blockIdx.x >> 5;
    int jt = blockIdx.x & 31;
    int bg0 = bt << 5;

    for (int i = tid; i < 3 * 8 * 256; i += 256) {
        int k2 = i & 255, jj2 = (i >> 8) & 7, g = i >> 11;
        int rA = g * HID + (jt << 4) + (jj2 << 1);
        ulonglong2 w;
        w.x = __ldg((const ull*)(Whh + (size_t)rA * HID) + k2);
        w.y = __ldg((const ull*)(Whh + (size_t)(rA + 1) * HID) + k2);
        ws2[i] = w;
    }

    int b = tid & 31;
    int jj = tid >> 5;
    int jA = (jt << 4) + (jj << 1);
    int jB = jA + 1;
    int bg = bg0 + b;

    float brA = __ldg(bhh + jA),           brB = __ldg(bhh + jB);
    float bzA = __ldg(bhh + HID + jA),     bzB = __ldg(bhh + HID + jB);
    float bnA = __ldg(bhh + 2 * HID + jA), bnB = __ldg(bhh + 2 * HID + jB);

    unsigned* ctr = &g_ctr[layer];

    // zero owned slice of h buffer 0
    {
        int k2z = (jt << 3) + (tid >> 5);
        g_h2[0][k2z * 128 + bg0 + (tid & 31)] = 0ULL;
    }
    __syncthreads();
    if (tid == 0) {
        bar_arrive(ctr);
        while (bar_poll(ctr) < 128u) {}
    }
    __syncthreads();

    const ulonglong2* wr = ws2 + (jj << 8);
    const ulonglong2* wz = ws2 + ((8 + jj) << 8);
    const ulonglong2* wn = ws2 + ((16 + jj) << 8);

    for (int t = 0; t < Tlen; t++) {
        int rb = t & 1, wb = rb ^ 1;

        // xg loads (coalesced along b)
        size_t xrow = (size_t)t * GATE * Bsz;
        float xrA = __ldg(g_xg + xrow + (size_t)jA * Bsz + bg);
        float xzA = __ldg(g_xg + xrow + (size_t)(HID + jA) * Bsz + bg);
        float xnA = __ldg(g_xg + xrow + (size_t)(2 * HID + jA) * Bsz + bg);
        float xrB = __ldg(g_xg + xrow + (size_t)jB * Bsz + bg);
        float xzB = __ldg(g_xg + xrow + (size_t)(HID + jB) * Bsz + bg);
        float xnB = __ldg(g_xg + xrow + (size_t)(2 * HID + jB) * Bsz + bg);

        // h tile load: 256 k2 x 32 b (this block) -> hsu[k2][b]
        const ulonglong2* hsrc = (const ulonglong2*)(g_h2[rb]);
        for (int i = tid; i < 4096; i += 256) {
            int k2 = i >> 4, q = i & 15;
            ulonglong2 v = __ldcg(hsrc + k2 * 64 + (bg0 >> 1) + q);
            *(ulonglong2*)(hsu + k2 * 34 + (q << 1)) = v;
        }
        __syncthreads();

        ull arA = pack2(brA, 0.0f), arB = pack2(brB, 0.0f);
        ull azA = pack2(bzA, 0.0f), azB = pack2(bzB, 0.0f);
        ull anA = pack2(bnA, 0.0f), anB = pack2(bnB, 0.0f);
        const ull* hp = hsu + b;
#pragma unroll 8
        for (int k2 = 0; k2 < 256; k2++) {
            ull h2 = hp[k2 * 34];
            ulonglong2 w = wr[k2];
            arA = fma2(w.x, h2, arA); arB = fma2(w.y, h2, arB);
            w = wz[k2];
            azA = fma2(w.x, h2, azA); azB = fma2(w.y, h2, azB);
            w = wn[k2];
            anA = fma2(w.x, h2, anA); anB = fma2(w.y, h2, anB);
        }
        float2 u;
        u = unpack2(arA); float hrA = u.x + u.y;
        u = unpack2(arB); float hrB = u.x + u.y;
        u = unpack2(azA); float hzA = u.x + u.y;
        u = unpack2(azB); float hzB = u.x + u.y;
        u = unpack2(anA); float hnA = u.x + u.y;
        u = unpack2(anB); float hnB = u.x + u.y;

        float2 hold = unpack2(hp[(jA >> 1) * 34]);   // (h[jA], h[jB])

        float rA = 1.0f / (1.0f + __expf(-(xrA + hrA)));
        float zA = 1.0f / (1.0f + __expf(-(xzA + hzA)));
        float nA = tanhf(xnA + rA * hnA);
        float hnewA = (1.0f - zA) * nA + zA * hold.x;

        float rB = 1.0f / (1.0f + __expf(-(xrB + hrB)));
        float zB = 1.0f / (1.0f + __expf(-(xzB + hzB)));
        float nB = tanhf(xnB + rB * hnB);
        float hnewB = (1.0f - zB) * nB + zB * hold.y;

        g_h2[wb][(jA >> 1) * 128 + bg] = pack2(hnewA, hnewB);
        if (layer == 0) {
            size_t srow = (size_t)t * HID * Bsz;
            g_hseq[srow + (size_t)jA * Bsz + bg] = hnewA;
            g_hseq[srow + (size_t)jB * Bsz + bg] = hnewB;
        }

        __syncthreads();
        if (tid == 0) {
            bar_arrive(ctr);
            unsigned target = 128u * (unsigned)(t + 2);
            while (bar_poll(ctr) < target) {}
        }
        __syncthreads();
    }
}

// ============================================================
__global__ __launch_bounds__(64) void out_k(
    const float* __restrict__ Wout, const float* __restrict__ bout,
    float* __restrict__ out)
{
    __shared__ float hrow[HID];
    int bg = blockIdx.x, tid = threadIdx.x;
    const float* hsrc = (const float*)g_h2[0];
    for (int i = tid; i < HID; i += 64)
        hrow[i] = hsrc[(((i >> 1) * 128 + bg) << 1) + (i & 1)];
    __syncthreads();
    float acc = __ldg(bout + tid);
    const float* w = Wout + (size_t)tid * HID;
#pragma unroll 8
    for (int j = 0; j < HID; j++) acc += hrow[j] * __ldg(w + j);
    out[bg * OUTN + tid] = acc;
}

// ============================================================
extern "C" void kernel_launch(void* const* d_in, const int* in_sizes, int n_in,
                              void* d_out, int out_size)
{
    const float* x     = (const float*)d_in[0];
    const float* W_ih0 = (const float*)d_in[1];
    const float* W_hh0 = (const float*)d_in[2];
    const float* b_ih0 = (const float*)d_in[3];
    const float* b_hh0 = (const float*)d_in[4];
    const float* W_ih1 = (const float*)d_in[5];
    const float* W_hh1 = (const float*)d_in[6];
    const float* b_ih1 = (const float*)d_in[7];
    const float* b_hh1 = (const float*)d_in[8];
    const float* W_out = (const float*)d_in[9];
    const float* b_out = (const float*)d_in[10];
    float* out = (float*)d_out;

    cudaFuncSetAttribute(recur_k, cudaFuncAttributeMaxDynamicSharedMemorySize, RECUR_SMEM);

    init_k<<<1, 32>>>();

    gemm_tc_k<<<dim3(GATE / 128, Tlen), 256, SM_GEMM_TOTAL>>>(x, W_ih0, b_ih0, INPUTK, 0);
    recur_k<<<128, 256, RECUR_SMEM>>>(W_hh0, b_hh0, 0);

    gemm_tc_k<<<dim3(GATE / 128, Tlen), 256, SM_GEMM_TOTAL>>>(nullptr, W_ih1, b_ih1, HID, 1);
    recur_k<<<128, 256, RECUR_SMEM>>>(W_hh1, b_hh1, 1);

    out_k<<<Bsz, OUTN>>>(W_out, b_out, out);
}